// round 5
// baseline (speedup 1.0000x reference)
#include <cuda_runtime.h>

#define NL 50
#define THREADS 256
#define SPLITS 4
#define MAX_B 4096

// Edge integers: E_i = i for i<=25, else 25 + 7*(i-25); E_50 = 200.
// Edge floats computed exactly as numpy: (double)n / 200.0 * 0.6, cast to f32.
constexpr int   edge_int(int i) { return i <= 25 ? i : 25 + 7 * (i - 25); }
constexpr float edge_f(int i)   { return (float)((double)edge_int(i) / 200.0 * 0.6); }

#define E1(a)  edge_f(a)
#define E4(a)  E1(a), E1(a+1), E1(a+2), E1(a+3)
#define E16(a) E4(a), E4(a+4), E4(a+8), E4(a+12)
__constant__ float c_edges[51] = { E16(0), E16(16), E16(32), E1(48), E1(49), E1(50) };

__device__ float        g_partial[MAX_B * SPLITS];
__device__ unsigned int g_count[MAX_B];   // zero-init; self-resetting

// tbl[c] = {lo=E_c, hi=E_{c+1}, w=w_c, 0}. Fast path: one LDS.128.
// wext[j+1]: zero-padded weights for the ulp-rare off-by-one fallback.
__device__ __forceinline__ float bin_weight(float z,
                                            const float4* __restrict__ tbl,
                                            const float*  __restrict__ wext)
{
    if (z >= 0.6f || z <= 0.0f) return 0.0f;       // outside all bins, no LDS
    float t = z * (200.0f / 0.6f);
    int c = (t < 25.0f) ? (int)t : 25 + (int)((t - 25.0f) * (1.0f / 7.0f));
    c = min(c, NL - 1);
    float4 q = tbl[c];
    float w = q.z;
    if (!(z > q.x && z < q.y)) {                   // candidate off by one (rare)
        int j = (z >= q.y) ? c + 1 : c - 1;        // j in [-1, 50]
        w = wext[j + 1];
    }
    return w;
}

__global__ __launch_bounds__(THREADS) void zws_kernel(
    const float4* __restrict__ x,      // (B, V/2) float4 = 2 (z,val) pairs
    const float*  __restrict__ weight, // (NL,)
    const float*  __restrict__ bias,   // (NL,)
    float*        __restrict__ out,    // (B,)
    int nf4_per_row)                   // V/2
{
    __shared__ float4 tbl[NL];
    __shared__ float  wext[NL + 2];
    __shared__ bool   is_last;

    const int tid = threadIdx.x;
    const int b   = blockIdx.x / SPLITS;
    const int s   = blockIdx.x % SPLITS;

    float acc = 0.0f;
    if (tid < NL) {
        float w = weight[tid];
        tbl[tid]      = make_float4(c_edges[tid], c_edges[tid + 1], w, 0.0f);
        wext[tid + 1] = w;
        if (s == 0) acc = bias[tid] * w;           // fold dot(bias, weight)
    }
    if (tid == 0)  { wext[0] = 0.0f; wext[NL + 1] = 0.0f; }
    __syncthreads();

    const int seg_len = (nf4_per_row + SPLITS - 1) / SPLITS;
    const int i_begin = s * seg_len;
    const int i_end   = min(i_begin + seg_len, nf4_per_row);

    const float4* row = x + (size_t)b * nf4_per_row;

    // Front-batch both loads, dependent work after.
    const int i0 = i_begin + tid;
    const int i1 = i0 + THREADS;
    float4 p0 = make_float4(0.f, 0.f, 0.f, 0.f);
    float4 p1 = make_float4(0.f, 0.f, 0.f, 0.f);
    if (i0 < i_end) p0 = __ldg(&row[i0]);
    if (i1 < i_end) p1 = __ldg(&row[i1]);

    acc = fmaf(p0.y, bin_weight(p0.x, tbl, wext), acc);
    acc = fmaf(p0.w, bin_weight(p0.z, tbl, wext), acc);
    acc = fmaf(p1.y, bin_weight(p1.x, tbl, wext), acc);
    acc = fmaf(p1.w, bin_weight(p1.z, tbl, wext), acc);

    // Tail beyond 2*THREADS per block (not hit for the standard shape).
    for (int i = i1 + THREADS; i < i_end; i += THREADS) {
        float4 p = __ldg(&row[i]);
        acc = fmaf(p.y, bin_weight(p.x, tbl, wext), acc);
        acc = fmaf(p.w, bin_weight(p.z, tbl, wext), acc);
    }

    // Block reduction
    #pragma unroll
    for (int o = 16; o; o >>= 1)
        acc += __shfl_down_sync(0xFFFFFFFFu, acc, o);

    __shared__ float red[THREADS / 32];
    if ((tid & 31) == 0) red[tid >> 5] = acc;
    __syncthreads();

    if (tid == 0) {
        float v = 0.0f;
        #pragma unroll
        for (int i = 0; i < THREADS / 32; ++i) v += red[i];
        g_partial[b * SPLITS + s] = v;
        __threadfence();
        unsigned int old = atomicAdd(&g_count[b], 1u);
        is_last = (old == SPLITS - 1);
    }
    __syncthreads();

    if (is_last && tid == 0) {
        __threadfence();
        volatile float* vp = &g_partial[b * SPLITS];
        float total = 0.0f;
        #pragma unroll
        for (int k = 0; k < SPLITS; ++k) total += vp[k];
        out[b] = total;
        g_count[b] = 0;   // reset for next graph replay
    }
}

extern "C" void kernel_launch(void* const* d_in, const int* in_sizes, int n_in,
                              void* d_out, int out_size)
{
    const float4* x      = (const float4*)d_in[0];  // (B, V, 2) float32
    const float*  weight = (const float*)d_in[1];   // (NL, 1)
    const float*  bias   = (const float*)d_in[2];   // (NL,)
    float*        out    = (float*)d_out;           // (B,)

    const int B = out_size;                          // 256
    const int pairs_total = in_sizes[0] / 2;         // B * V
    const int nf4_per_row = pairs_total / B / 2;     // V / 2 = 2048

    zws_kernel<<<B * SPLITS, THREADS>>>(x, weight, bias, out, nf4_per_row);
}